// round 1
// baseline (speedup 1.0000x reference)
#include <cuda_runtime.h>
#include <cstdint>

#define N_NODES_MAX 50000
#define IN_FEATS 128
#define N_HIDDEN 128
#define N_CLASSES 64

// Scratch buffers (no device allocation allowed).
__device__ float g_h[N_NODES_MAX * N_HIDDEN];    // GEMM output (pre-aggregation)
__device__ float g_agg[N_NODES_MAX * N_HIDDEN];  // aggregation output (layers 1,2)

// out[row, j] = sum_k act(in[row, k]) * W[k, j] + b[j]
// blockDim.x = F_OUT threads; each block handles RB rows.
template <int F_IN, int F_OUT, bool RELU_IN, int RB>
__global__ void linear_kernel(const float* __restrict__ in,
                              const float* __restrict__ Wm,
                              const float* __restrict__ bv,
                              float* __restrict__ out, int n_rows) {
    __shared__ float hs[RB][F_IN];
    const int row0 = blockIdx.x * RB;
    const int tid = threadIdx.x;

    // Cooperative load of RB input rows (ReLU folded in).
    #pragma unroll
    for (int i = tid; i < RB * F_IN; i += F_OUT) {
        int r = i / F_IN;
        int c = i - r * F_IN;
        int row = row0 + r;
        float v = (row < n_rows) ? in[(size_t)row * F_IN + c] : 0.0f;
        if (RELU_IN) v = fmaxf(v, 0.0f);
        hs[r][c] = v;
    }
    __syncthreads();

    float acc[RB];
    #pragma unroll
    for (int r = 0; r < RB; r++) acc[r] = 0.0f;

    #pragma unroll 4
    for (int k = 0; k < F_IN; k++) {
        float wv = __ldg(Wm + (size_t)k * F_OUT + tid);
        #pragma unroll
        for (int r = 0; r < RB; r++) acc[r] += hs[r][k] * wv;
    }

    float bb = __ldg(bv + tid);
    #pragma unroll
    for (int r = 0; r < RB; r++) {
        int row = row0 + r;
        if (row < n_rows) out[(size_t)row * F_OUT + tid] = acc[r] + bb;
    }
}

// For each edge e: out[dst[e], :] += h[src[e], :] * w[e]
// F/4 threads cooperate on one edge; float4 gather + v4 vector global reduction.
template <int F>
__global__ void scatter_kernel(const float* __restrict__ h,
                               const float* __restrict__ w,
                               const int* __restrict__ src,
                               const int* __restrict__ dst,
                               float* __restrict__ out, int n_edges) {
    constexpr int LANES = F / 4;
    int gid = blockIdx.x * blockDim.x + threadIdx.x;
    int edge = gid / LANES;
    int lane = gid - edge * LANES;
    if (edge >= n_edges) return;

    int s = __ldg(src + edge);
    int d = __ldg(dst + edge);
    float ww = __ldg(w + edge);

    float4 v = __ldg(reinterpret_cast<const float4*>(h + (size_t)s * F) + lane);
    v.x *= ww; v.y *= ww; v.z *= ww; v.w *= ww;

    float* op = out + (size_t)d * F + (size_t)lane * 4;
    asm volatile("red.global.add.v4.f32 [%0], {%1, %2, %3, %4};"
                 :: "l"(op), "f"(v.x), "f"(v.y), "f"(v.z), "f"(v.w)
                 : "memory");
}

extern "C" void kernel_launch(void* const* d_in, const int* in_sizes, int n_in,
                              void* d_out, int out_size) {
    const float* x  = (const float*)d_in[0];
    const float* w  = (const float*)d_in[1];
    const int*   src = (const int*)d_in[2];
    const int*   dst = (const int*)d_in[3];
    const float* W1 = (const float*)d_in[4];
    const float* b1 = (const float*)d_in[5];
    const float* W2 = (const float*)d_in[6];
    const float* b2 = (const float*)d_in[7];
    const float* W3 = (const float*)d_in[8];
    const float* b3 = (const float*)d_in[9];
    float* out = (float*)d_out;

    const int n_nodes = in_sizes[0] / IN_FEATS;
    const int n_edges = in_sizes[1];

    float *h_buf = nullptr, *agg_buf = nullptr;
    cudaGetSymbolAddress((void**)&h_buf, g_h);
    cudaGetSymbolAddress((void**)&agg_buf, g_agg);

    constexpr int RB = 8;
    const int gemm_blocks = (n_nodes + RB - 1) / RB;

    const int sc128_threads = n_edges * (N_HIDDEN / 4);
    const int sc128_blocks = (sc128_threads + 255) / 256;
    const int sc64_threads = n_edges * (N_CLASSES / 4);
    const int sc64_blocks = (sc64_threads + 255) / 256;

    // ---- Layer 1 ----
    linear_kernel<IN_FEATS, N_HIDDEN, false, RB>
        <<<gemm_blocks, N_HIDDEN>>>(x, W1, b1, h_buf, n_nodes);
    cudaMemsetAsync(agg_buf, 0, (size_t)n_nodes * N_HIDDEN * sizeof(float), 0);
    scatter_kernel<N_HIDDEN>
        <<<sc128_blocks, 256>>>(h_buf, w, src, dst, agg_buf, n_edges);

    // ---- Layer 2 (ReLU folded into GEMM input load) ----
    linear_kernel<N_HIDDEN, N_HIDDEN, true, RB>
        <<<gemm_blocks, N_HIDDEN>>>(agg_buf, W2, b2, h_buf, n_nodes);
    cudaMemsetAsync(agg_buf, 0, (size_t)n_nodes * N_HIDDEN * sizeof(float), 0);
    scatter_kernel<N_HIDDEN>
        <<<sc128_blocks, 256>>>(h_buf, w, src, dst, agg_buf, n_edges);

    // ---- Layer 3 (output 64-wide, straight into d_out) ----
    linear_kernel<N_HIDDEN, N_CLASSES, true, RB>
        <<<gemm_blocks, N_CLASSES>>>(agg_buf, W3, b3, h_buf, n_nodes);
    cudaMemsetAsync(out, 0, (size_t)out_size * sizeof(float), 0);
    scatter_kernel<N_CLASSES>
        <<<sc64_blocks, 256>>>(h_buf, w, src, dst, out, n_edges);
}